// round 15
// baseline (speedup 1.0000x reference)
#include <cuda_runtime.h>
#include <cuda_fp16.h>
#include <math.h>
#include <stdint.h>

#define BATCH 2
#define SEQ   2048
#define DIM   4096
#define HQ    32
#define HK    8
#define HD    128
#define REP   4
#define MROWS (BATCH*SEQ)   // 4096
#define QSCALE 0.08838834764831845f

// fp16 planes (row-major [M,K])
__device__ __half g_Xf [(size_t)MROWS*DIM];
__device__ __half g_Wqf[(size_t)DIM*HQ*HD];
__device__ __half g_Wkf[(size_t)DIM*HK*HD];
__device__ __half g_Wvf[(size_t)DIM*HK*HD];
__device__ __half g_Wof[(size_t)DIM*DIM];
__device__ __half g_Qf [(size_t)MROWS*HQ*HD];
__device__ __half g_Kf [(size_t)MROWS*HK*HD];
__device__ __half g_Vf [(size_t)MROWS*HK*HD];
__device__ __half g_AOf[(size_t)MROWS*HQ*HD];

// ---------------- PTX helpers ----------------
#define LDSM4(R0,R1,R2,R3,A) \
    asm volatile("ldmatrix.sync.aligned.m8n8.x4.shared.b16 {%0,%1,%2,%3},[%4];" \
        : "=r"(R0),"=r"(R1),"=r"(R2),"=r"(R3) : "r"(A))
#define LDSM4T(R0,R1,R2,R3,A) \
    asm volatile("ldmatrix.sync.aligned.m8n8.x4.trans.shared.b16 {%0,%1,%2,%3},[%4];" \
        : "=r"(R0),"=r"(R1),"=r"(R2),"=r"(R3) : "r"(A))
#define MMAF16(D,A0,A1,A2,A3,B0,B1) \
    asm volatile("mma.sync.aligned.m16n8k16.row.col.f32.f16.f16.f32 " \
        "{%0,%1,%2,%3},{%4,%5,%6,%7},{%8,%9},{%0,%1,%2,%3};" \
        : "+f"(D[0]), "+f"(D[1]), "+f"(D[2]), "+f"(D[3]) \
        : "r"(A0),"r"(A1),"r"(A2),"r"(A3),"r"(B0),"r"(B1))
#define CP16(DST,SRC) \
    asm volatile("cp.async.cg.shared.global [%0],[%1],16;" :: "r"(DST),"l"(SRC))
#define CP_COMMIT asm volatile("cp.async.commit_group;" ::: "memory")
#define CP_WAIT2  asm volatile("cp.async.wait_group 2;" ::: "memory")
#define CP_WAIT1  asm volatile("cp.async.wait_group 1;" ::: "memory")
#define CP_WAIT0  asm volatile("cp.async.wait_group 0;" ::: "memory")

__device__ __forceinline__ uint32_t smem_u32(const void* p) {
    return (uint32_t)__cvta_generic_to_shared(p);
}
__device__ __forceinline__ uint32_t pack2h(float x0, float x1) {
    __half2 h = __floats2half2_rn(x0, x1);
    return *(uint32_t*)&h;
}

// ---------------------------------------------------------------------------
// fp32 -> fp16 convert, MLP=4. Segment by blockIdx.y.
// ---------------------------------------------------------------------------
#define CN_X  4194304
#define CN_WQ 4194304
#define CN_WK 1048576
#define CN_WV 1048576
#define CN_WO 4194304

__global__ void cvt5(const float* __restrict__ x,  const float* __restrict__ wq,
                     const float* __restrict__ wk, const float* __restrict__ wv,
                     const float* __restrict__ wo)
{
    int seg = blockIdx.y;
    const float* src; __half* dst; int n4;
    if (seg == 0)      { src = x;  dst = g_Xf;  n4 = CN_X;  }
    else if (seg == 1) { src = wq; dst = g_Wqf; n4 = CN_WQ; }
    else if (seg == 2) { src = wk; dst = g_Wkf; n4 = CN_WK; }
    else if (seg == 3) { src = wv; dst = g_Wvf; n4 = CN_WV; }
    else               { src = wo; dst = g_Wof; n4 = CN_WO; }

    const int step = gridDim.x * blockDim.x;   // 262144 (divides all n4)
    int i = blockIdx.x * blockDim.x + threadIdx.x;
    for (; i + 3*step < n4; i += 4*step) {
        float4 v0 = ((const float4*)src)[i];
        float4 v1 = ((const float4*)src)[i + step];
        float4 v2 = ((const float4*)src)[i + 2*step];
        float4 v3 = ((const float4*)src)[i + 3*step];
        ((uint2*)dst)[i]          = make_uint2(pack2h(v0.x,v0.y), pack2h(v0.z,v0.w));
        ((uint2*)dst)[i + step]   = make_uint2(pack2h(v1.x,v1.y), pack2h(v1.z,v1.w));
        ((uint2*)dst)[i + 2*step] = make_uint2(pack2h(v2.x,v2.y), pack2h(v2.z,v2.w));
        ((uint2*)dst)[i + 3*step] = make_uint2(pack2h(v3.x,v3.y), pack2h(v3.z,v3.w));
    }
    for (; i < n4; i += step) {
        float4 v = ((const float4*)src)[i];
        ((uint2*)dst)[i] = make_uint2(pack2h(v.x,v.y), pack2h(v.z,v.w));
    }
}

// ---------------------------------------------------------------------------
// fp16 GEMM, 128x128x32 tile, 256 thr, 3-stage cp.async, occ 2.
// R15: ALL 12 fragment LDSMs per kt issued up front (volatile order was
// serializing each B-fragment load before its MMAs). Load hoisting only:
// accumulator update order unchanged -> bitwise-identical output.
// ---------------------------------------------------------------------------
#define G_SA 40
#define G_SB 136
#define G_B  5120
#define G_ST 9472
#define GEMM_SMEM3 (3*G_ST*2)

template<int QKV>
__global__ __launch_bounds__(256,2) void gemm3(
    const __half* __restrict__ Ap,
    const __half* __restrict__ Bp_,
    float* __restrict__ C,
    const float* __restrict__ cosv, const float* __restrict__ sinv,
    int M, int N_, int K)
{
    extern __shared__ __align__(16) __half smg[];
    const uint32_t smb = smem_u32(smg);

    const int tid  = threadIdx.x;
    const int br = blockIdx.y, bc = blockIdx.x;
    const int warp = tid >> 5, lane = tid & 31;
    const int wr = warp & 3, wc = warp >> 2;

    const __half* Bp;
    __half* Of = nullptr;
    int Nl, bcl;
    bool doRope = false;
    float scale = 1.f;
    if (QKV) {
        if (bc < 32)      { Bp = g_Wqf; Of = g_Qf; Nl = HQ*HD; bcl = bc;
                            doRope = true; scale = QSCALE; }
        else if (bc < 40) { Bp = g_Wkf; Of = g_Kf; Nl = HK*HD; bcl = bc - 32;
                            doRope = true; }
        else              { Bp = g_Wvf; Of = g_Vf; Nl = HK*HD; bcl = bc - 40; }
    } else { Bp = Bp_; Nl = N_; bcl = bc; }

    float acc[2][8][4];
#pragma unroll
    for (int i = 0; i < 2; i++)
#pragma unroll
        for (int j = 0; j < 8; j++)
#pragma unroll
            for (int r = 0; r < 4; r++) acc[i][j][r] = 0.f;

    const int a_row = (lane & 7) + 8 * ((lane >> 3) & 1);
    const int a_k   = 8 * (lane >> 4);
    const int b_kr  = (lane & 7) + 8 * ((lane >> 3) & 1);
    const int b_n   = 8 * (lane >> 4);

    const int nkt = K / 32;

    const int ar0 = tid >> 2, ac0 = (tid & 3) * 8;
    const int bk0 = tid >> 4, bn0 = (tid & 15) * 8;
#define GEMM_ISSUE(KT, BUF) do {                                               \
    int _sb = (BUF) * G_ST;                                                    \
    _Pragma("unroll")                                                          \
    for (int _j = 0; _j < 2; _j++) {                                           \
        int _r = ar0 + _j * 64;                                                \
        size_t _go = (size_t)(br*128 + _r) * K + (KT)*32 + ac0;                \
        CP16(smb + (_sb + _r*G_SA + ac0)*2, Ap + _go);                         \
        int _k = bk0 + _j * 16;                                                \
        size_t _gb = (size_t)((KT)*32 + _k) * Nl + bcl*128 + bn0;              \
        CP16(smb + (_sb + G_B + _k*G_SB + bn0)*2, Bp + _gb);                   \
    } } while (0)

    GEMM_ISSUE(0, 0); CP_COMMIT;
    GEMM_ISSUE(1, 1); CP_COMMIT;
    GEMM_ISSUE(2, 2); CP_COMMIT;

    int buf = 0;
    for (int kt = 0; kt < nkt; kt++) {
        if (kt < nkt - 2)      { CP_WAIT2; }
        else if (kt == nkt - 2){ CP_WAIT1; }
        else                   { CP_WAIT0; }
        __syncthreads();
        const int sb = buf * G_ST;

        // --- issue ALL fragment loads for both ks-steps up front ---
        uint32_t af[2][2][4], bf[2][4][4];
#pragma unroll
        for (int ks = 0; ks < 2; ks++) {
#pragma unroll
            for (int i = 0; i < 2; i++) {
                uint32_t addr = smb + (sb +
                    (wr*32 + i*16 + a_row)*G_SA + ks*16 + a_k) * 2;
                LDSM4(af[ks][i][0], af[ks][i][1], af[ks][i][2], af[ks][i][3], addr);
            }
#pragma unroll
            for (int jp = 0; jp < 4; jp++) {
                uint32_t addr = smb + (sb + G_B +
                    (ks*16 + b_kr)*G_SB + wc*64 + jp*16 + b_n) * 2;
                LDSM4T(bf[ks][jp][0], bf[ks][jp][1], bf[ks][jp][2], bf[ks][jp][3], addr);
            }
        }
        // --- 32 MMAs, same accumulator order as before ---
#pragma unroll
        for (int ks = 0; ks < 2; ks++) {
#pragma unroll
            for (int jp = 0; jp < 4; jp++) {
#pragma unroll
                for (int i = 0; i < 2; i++) {
#pragma unroll
                    for (int jj = 0; jj < 2; jj++)
                        MMAF16(acc[i][2*jp + jj],
                               af[ks][i][0],af[ks][i][1],af[ks][i][2],af[ks][i][3],
                               bf[ks][jp][2*jj], bf[ks][jp][2*jj+1]);
                }
            }
        }
        __syncthreads();
        if (kt + 3 < nkt) { GEMM_ISSUE(kt + 3, buf); CP_COMMIT; }
        buf = (buf == 2) ? 0 : buf + 1;
    }

    const int g = lane >> 2, t = lane & 3;
#pragma unroll
    for (int i = 0; i < 2; i++) {
#pragma unroll
        for (int j = 0; j < 8; j++) {
            int row = br*128 + wr*32 + i*16 + g;
            int col = bcl*128 + wc*64 + j*8 + 2*t;
            float a0 = acc[i][j][0], a1 = acc[i][j][1];
            float a2 = acc[i][j][2], a3 = acc[i][j][3];
            if (QKV) {
                if (doRope) {
                    int s0 = row & (SEQ-1), s1 = (row+8) & (SEQ-1);
                    int d2 = (col & (HD-1)) >> 1;
                    float c0 = cosv[s0*64 + d2], sn0 = sinv[s0*64 + d2];
                    float c1 = cosv[s1*64 + d2], sn1 = sinv[s1*64 + d2];
                    float r;
                    r  = (a0*c0 - a1*sn0) * scale;
                    a1 = (a0*sn0 + a1*c0) * scale;  a0 = r;
                    r  = (a2*c1 - a3*sn1) * scale;
                    a3 = (a2*sn1 + a3*c1) * scale;  a2 = r;
                }
                *(uint32_t*)&Of[(size_t)row * Nl + col]     = pack2h(a0, a1);
                *(uint32_t*)&Of[(size_t)(row+8) * Nl + col] = pack2h(a2, a3);
            } else {
                *(float2*)&C[(size_t)row * Nl + col] = make_float2(a0, a1);
                *(float2*)&C[(size_t)(row+8) * Nl + col] = make_float2(a2, a3);
            }
        }
    }
}

// ---------------------------------------------------------------------------
// fp16 flash attention (R9 base, occ 2). R15: K fragments double-buffered
// across sp, V fragments across np (load hoisting only -> bitwise-identical).
// ---------------------------------------------------------------------------
#define F_S   136
#define F_STG 17408
#define F_V   8704
#define F_SST 17408
#define FLASH_SMEM ((F_STG + 2*F_SST)*2)

__global__ __launch_bounds__(256,2) void flash_f16(
    const __half* __restrict__ Qf, const __half* __restrict__ Kf,
    const __half* __restrict__ Vf, __half* __restrict__ AOf)
{
    extern __shared__ __align__(16) __half smf[];
    const uint32_t smb = smem_u32(smf);

    const int tid = threadIdx.x;
    const int w = tid >> 5, lane = tid & 31;
    const int q0 = blockIdx.x * 128;
    const int b  = blockIdx.y >> 5;
    const int h  = blockIdx.y & 31;
    const int g  = h >> 2;

#pragma unroll
    for (int it = 0; it < 8; it++) {
        int idx = tid + it * 256;
        int r = idx >> 4, cc = (idx & 15) * 8;
        size_t go = ((size_t)((b*SEQ + q0 + r) * HQ + h)) * HD + cc;
        CP16(smb + (r*F_S + cc)*2, Qf + go);
    }
#define FLASH_ISSUE_KV(KB, BUF) do {                                           \
    int _sb = F_STG + (BUF) * F_SST;                                           \
    _Pragma("unroll")                                                          \
    for (int _it = 0; _it < 4; _it++) {                                        \
        int _idx = tid + _it * 256;                                            \
        int _r = _idx >> 4, _c = (_idx & 15) * 8;                              \
        size_t _go = ((size_t)((b*SEQ + (KB)*64 + _r) * HK + g)) * HD + _c;    \
        CP16(smb + (_sb + _r*F_S + _c)*2, Kf + _go);                           \
        CP16(smb + (_sb + F_V + _r*F_S + _c)*2, Vf + _go);                     \
    } } while (0)

    FLASH_ISSUE_KV(0, 0); CP_COMMIT;
    FLASH_ISSUE_KV(1, 1); CP_COMMIT;

    float oacc[16][4];
#pragma unroll
    for (int n = 0; n < 16; n++)
#pragma unroll
        for (int r = 0; r < 4; r++) oacc[n][r] = 0.f;
    float m0 = -1e30f, m1 = -1e30f, l0 = 0.f, l1 = 0.f;

    const int q_row = w*16 + (lane & 7) + 8*((lane >> 3) & 1);
    const int q_k   = 8 * (lane >> 4);
    const int k_row = (lane & 7) + 8*(lane >> 4);
    const int k_d   = 8 * ((lane >> 3) & 1);
    const int v_row = (lane & 7) + 8*((lane >> 3) & 1);
    const int v_d   = 8 * (lane >> 4);

    const int NKB = SEQ / 64;
    for (int kb = 0; kb < NKB; kb++) {
        if (kb < NKB - 2) { CP_WAIT1; } else { CP_WAIT0; }
        __syncthreads();
        const int sb = F_STG + (kb & 1) * F_SST;

        float sacc[8][4];
#pragma unroll
        for (int j = 0; j < 8; j++)
#pragma unroll
            for (int r = 0; r < 4; r++) sacc[j][r] = 0.f;

#pragma unroll
        for (int dks = 0; dks < 8; dks++) {
            uint32_t qf[4];
            uint32_t qa = smb + (q_row*F_S + dks*16 + q_k) * 2;
            LDSM4(qf[0], qf[1], qf[2], qf[3], qa);
            uint32_t kf2[2][4];
            {
                uint32_t ka = smb + (sb + (0*16 + k_row)*F_S + dks*16 + k_d) * 2;
                LDSM4(kf2[0][0], kf2[0][1], kf2[0][2], kf2[0][3], ka);
            }
#pragma unroll
            for (int sp = 0; sp < 4; sp++) {
                if (sp < 3) {
                    uint32_t ka = smb + (sb + ((sp+1)*16 + k_row)*F_S + dks*16 + k_d) * 2;
                    LDSM4(kf2[(sp+1)&1][0], kf2[(sp+1)&1][1],
                          kf2[(sp+1)&1][2], kf2[(sp+1)&1][3], ka);
                }
                const uint32_t* kfr = kf2[sp & 1];
#pragma unroll
                for (int jj = 0; jj < 2; jj++)
                    MMAF16(sacc[2*sp + jj], qf[0],qf[1],qf[2],qf[3],
                           kfr[2*jj], kfr[2*jj+1]);
            }
        }

        float mx0 = m0, mx1 = m1;
#pragma unroll
        for (int j = 0; j < 8; j++) {
            mx0 = fmaxf(mx0, fmaxf(sacc[j][0], sacc[j][1]));
            mx1 = fmaxf(mx1, fmaxf(sacc[j][2], sacc[j][3]));
        }
        mx0 = fmaxf(mx0, __shfl_xor_sync(0xffffffffu, mx0, 1));
        mx0 = fmaxf(mx0, __shfl_xor_sync(0xffffffffu, mx0, 2));
        mx1 = fmaxf(mx1, __shfl_xor_sync(0xffffffffu, mx1, 1));
        mx1 = fmaxf(mx1, __shfl_xor_sync(0xffffffffu, mx1, 2));
        float sf0 = __expf(m0 - mx0), sf1 = __expf(m1 - mx1);
        m0 = mx0; m1 = mx1;
        float rs0 = 0.f, rs1 = 0.f;
#pragma unroll
        for (int j = 0; j < 8; j++) {
            sacc[j][0] = __expf(sacc[j][0] - m0);
            sacc[j][1] = __expf(sacc[j][1] - m0);
            sacc[j][2] = __expf(sacc[j][2] - m1);
            sacc[j][3] = __expf(sacc[j][3] - m1);
            rs0 += sacc[j][0] + sacc[j][1];
            rs1 += sacc[j][2] + sacc[j][3];
        }
        rs0 += __shfl_xor_sync(0xffffffffu, rs0, 1);
        rs0 += __shfl_xor_sync(0xffffffffu, rs0, 2);
        rs1 += __shfl_xor_sync(0xffffffffu, rs1, 1);
        rs1 += __shfl_xor_sync(0xffffffffu, rs1, 2);
        l0 = l0 * sf0 + rs0;
        l1 = l1 * sf1 + rs1;
#pragma unroll
        for (int n = 0; n < 16; n++) {
            oacc[n][0] *= sf0; oacc[n][1] *= sf0;
            oacc[n][2] *= sf1; oacc[n][3] *= sf1;
        }

#pragma unroll
        for (int ks = 0; ks < 4; ks++) {
            uint32_t ph[4];
            ph[0] = pack2h(sacc[2*ks  ][0], sacc[2*ks  ][1]);
            ph[1] = pack2h(sacc[2*ks  ][2], sacc[2*ks  ][3]);
            ph[2] = pack2h(sacc[2*ks+1][0], sacc[2*ks+1][1]);
            ph[3] = pack2h(sacc[2*ks+1][2], sacc[2*ks+1][3]);
            uint32_t vf2[2][4];
            {
                uint32_t va = smb + (sb + F_V + (ks*16 + v_row)*F_S + 0*16 + v_d) * 2;
                LDSM4T(vf2[0][0], vf2[0][1], vf2[0][2], vf2[0][3], va);
            }
#pragma unroll
            for (int np = 0; np < 8; np++) {
                if (np < 7) {
                    uint32_t va = smb + (sb + F_V + (ks*16 + v_row)*F_S + (np+1)*16 + v_d) * 2;
                    LDSM4T(vf2[(np+1)&1][0], vf2[(np+1)&1][1],
                           vf2[(np+1)&1][2], vf2[(np+1)&1][3], va);
                }
                const uint32_t* vf = vf2[np & 1];
#pragma unroll
                for (int jj = 0; jj < 2; jj++)
                    MMAF16(oacc[2*np + jj], ph[0],ph[1],ph[2],ph[3],
                           vf[2*jj], vf[2*jj+1]);
            }
        }
        __syncthreads();
        if (kb + 2 < NKB) { FLASH_ISSUE_KV(kb + 2, kb & 1); CP_COMMIT; }
    }

    float il0 = 1.f / l0, il1 = 1.f / l1;
    const int ga = lane >> 2, t = lane & 3;
    const int qa = q0 + w*16 + ga;
#pragma unroll
    for (int n = 0; n < 16; n++) {
        int col = n*8 + 2*t;
        size_t base0 = ((size_t)((b*SEQ + qa)     * HQ + h)) * HD + col;
        size_t base1 = ((size_t)((b*SEQ + qa + 8) * HQ + h)) * HD + col;
        *(uint32_t*)&AOf[base0] = pack2h(oacc[n][0]*il0, oacc[n][1]*il0);
        *(uint32_t*)&AOf[base1] = pack2h(oacc[n][2]*il1, oacc[n][3]*il1);
    }
}

// ---------------------------------------------------------------------------
extern "C" void kernel_launch(void* const* d_in, const int* in_sizes, int n_in,
                              void* d_out, int out_size)
{
    const float* x    = (const float*)d_in[0];
    const float* wq   = (const float*)d_in[1];
    const float* wk   = (const float*)d_in[2];
    const float* wv   = (const float*)d_in[3];
    const float* wo   = (const float*)d_in[4];
    const float* fcos = (const float*)d_in[5];
    const float* fsin = (const float*)d_in[6];
    float* out = (float*)d_out;

    __half *Xf,*Wof,*Qf,*Kf,*Vf,*AOf;
    cudaGetSymbolAddress((void**)&Xf,  g_Xf);
    cudaGetSymbolAddress((void**)&Wof, g_Wof);
    cudaGetSymbolAddress((void**)&Qf,  g_Qf);
    cudaGetSymbolAddress((void**)&Kf,  g_Kf);
    cudaGetSymbolAddress((void**)&Vf,  g_Vf);
    cudaGetSymbolAddress((void**)&AOf, g_AOf);

    cudaFuncSetAttribute(gemm3<0>,  cudaFuncAttributeMaxDynamicSharedMemorySize, GEMM_SMEM3);
    cudaFuncSetAttribute(gemm3<1>,  cudaFuncAttributeMaxDynamicSharedMemorySize, GEMM_SMEM3);
    cudaFuncSetAttribute(flash_f16, cudaFuncAttributeMaxDynamicSharedMemorySize, FLASH_SMEM);

    // input conversion, MLP-4, one launch (grid.y = segment)
    cvt5<<<dim3(1024, 5), 256>>>(x, wq, wk, wv, wo);

    // fused QKV projection (rope + fp16 epilogues)
    gemm3<1><<<dim3(48, MROWS/128), 256, GEMM_SMEM3>>>(
        Xf, nullptr, nullptr, fcos, fsin, MROWS, 0, DIM);

    // flash attention -> AO fp16 plane (occupancy 2)
    flash_f16<<<dim3(SEQ/128, BATCH*HQ), 256, FLASH_SMEM>>>(Qf, Kf, Vf, AOf);

    // output projection (fp32 out)
    gemm3<0><<<dim3(DIM/128, MROWS/128), 256, GEMM_SMEM3>>>(
        AOf, Wof, out, nullptr, nullptr, MROWS, DIM, DIM);
}

// round 16
// speedup vs baseline: 1.0590x; 1.0590x over previous
#include <cuda_runtime.h>
#include <cuda_fp16.h>
#include <math.h>
#include <stdint.h>

#define BATCH 2
#define SEQ   2048
#define DIM   4096
#define HQ    32
#define HK    8
#define HD    128
#define REP   4
#define MROWS (BATCH*SEQ)   // 4096
#define QSCALE 0.08838834764831845f

// fp16 planes (row-major [M,K])
__device__ __half g_Xf [(size_t)MROWS*DIM];
__device__ __half g_Wqf[(size_t)DIM*HQ*HD];
__device__ __half g_Wkf[(size_t)DIM*HK*HD];
__device__ __half g_Wvf[(size_t)DIM*HK*HD];
__device__ __half g_Wof[(size_t)DIM*DIM];
__device__ __half g_Qf [(size_t)MROWS*HQ*HD];
__device__ __half g_Kf [(size_t)MROWS*HK*HD];
__device__ __half g_Vf [(size_t)MROWS*HK*HD];
__device__ __half g_AOf[(size_t)MROWS*HQ*HD];

// ---------------- PTX helpers ----------------
#define LDSM4(R0,R1,R2,R3,A) \
    asm volatile("ldmatrix.sync.aligned.m8n8.x4.shared.b16 {%0,%1,%2,%3},[%4];" \
        : "=r"(R0),"=r"(R1),"=r"(R2),"=r"(R3) : "r"(A))
#define LDSM4T(R0,R1,R2,R3,A) \
    asm volatile("ldmatrix.sync.aligned.m8n8.x4.trans.shared.b16 {%0,%1,%2,%3},[%4];" \
        : "=r"(R0),"=r"(R1),"=r"(R2),"=r"(R3) : "r"(A))
#define MMAF16(D,A0,A1,A2,A3,B0,B1) \
    asm volatile("mma.sync.aligned.m16n8k16.row.col.f32.f16.f16.f32 " \
        "{%0,%1,%2,%3},{%4,%5,%6,%7},{%8,%9},{%0,%1,%2,%3};" \
        : "+f"(D[0]), "+f"(D[1]), "+f"(D[2]), "+f"(D[3]) \
        : "r"(A0),"r"(A1),"r"(A2),"r"(A3),"r"(B0),"r"(B1))
#define CP16(DST,SRC) \
    asm volatile("cp.async.cg.shared.global [%0],[%1],16;" :: "r"(DST),"l"(SRC))
#define CP_COMMIT asm volatile("cp.async.commit_group;" ::: "memory")
#define CP_WAIT2  asm volatile("cp.async.wait_group 2;" ::: "memory")
#define CP_WAIT1  asm volatile("cp.async.wait_group 1;" ::: "memory")
#define CP_WAIT0  asm volatile("cp.async.wait_group 0;" ::: "memory")

__device__ __forceinline__ uint32_t smem_u32(const void* p) {
    return (uint32_t)__cvta_generic_to_shared(p);
}
__device__ __forceinline__ uint32_t pack2h(float x0, float x1) {
    __half2 h = __floats2half2_rn(x0, x1);
    return *(uint32_t*)&h;
}

// ---------------------------------------------------------------------------
// fp32 -> fp16 convert, MLP=4. Segment by blockIdx.y.
// ---------------------------------------------------------------------------
#define CN_X  4194304
#define CN_WQ 4194304
#define CN_WK 1048576
#define CN_WV 1048576
#define CN_WO 4194304

__global__ void cvt5(const float* __restrict__ x,  const float* __restrict__ wq,
                     const float* __restrict__ wk, const float* __restrict__ wv,
                     const float* __restrict__ wo)
{
    int seg = blockIdx.y;
    const float* src; __half* dst; int n4;
    if (seg == 0)      { src = x;  dst = g_Xf;  n4 = CN_X;  }
    else if (seg == 1) { src = wq; dst = g_Wqf; n4 = CN_WQ; }
    else if (seg == 2) { src = wk; dst = g_Wkf; n4 = CN_WK; }
    else if (seg == 3) { src = wv; dst = g_Wvf; n4 = CN_WV; }
    else               { src = wo; dst = g_Wof; n4 = CN_WO; }

    const int step = gridDim.x * blockDim.x;   // 262144 (divides all n4)
    int i = blockIdx.x * blockDim.x + threadIdx.x;
    for (; i + 3*step < n4; i += 4*step) {
        float4 v0 = ((const float4*)src)[i];
        float4 v1 = ((const float4*)src)[i + step];
        float4 v2 = ((const float4*)src)[i + 2*step];
        float4 v3 = ((const float4*)src)[i + 3*step];
        ((uint2*)dst)[i]          = make_uint2(pack2h(v0.x,v0.y), pack2h(v0.z,v0.w));
        ((uint2*)dst)[i + step]   = make_uint2(pack2h(v1.x,v1.y), pack2h(v1.z,v1.w));
        ((uint2*)dst)[i + 2*step] = make_uint2(pack2h(v2.x,v2.y), pack2h(v2.z,v2.w));
        ((uint2*)dst)[i + 3*step] = make_uint2(pack2h(v3.x,v3.y), pack2h(v3.z,v3.w));
    }
    for (; i < n4; i += step) {
        float4 v = ((const float4*)src)[i];
        ((uint2*)dst)[i] = make_uint2(pack2h(v.x,v.y), pack2h(v.z,v.w));
    }
}

// ---------------------------------------------------------------------------
// fp16 GEMM (R9/R14-proven), 128x128x32 tile, 256 thr, 3-stage cp.async,
// occ 2. QKV=1: fused Q/K/V projection + rope epilogue. QKV=0: A@B -> fp32 C.
// ---------------------------------------------------------------------------
#define G_SA 40
#define G_SB 136
#define G_B  5120
#define G_ST 9472
#define GEMM_SMEM3 (3*G_ST*2)

template<int QKV>
__global__ __launch_bounds__(256,2) void gemm3(
    const __half* __restrict__ Ap,
    const __half* __restrict__ Bp_,
    float* __restrict__ C,
    const float* __restrict__ cosv, const float* __restrict__ sinv,
    int M, int N_, int K)
{
    extern __shared__ __align__(16) __half smg[];
    const uint32_t smb = smem_u32(smg);

    const int tid  = threadIdx.x;
    const int br = blockIdx.y, bc = blockIdx.x;
    const int warp = tid >> 5, lane = tid & 31;
    const int wr = warp & 3, wc = warp >> 2;

    const __half* Bp;
    __half* Of = nullptr;
    int Nl, bcl;
    bool doRope = false;
    float scale = 1.f;
    if (QKV) {
        if (bc < 32)      { Bp = g_Wqf; Of = g_Qf; Nl = HQ*HD; bcl = bc;
                            doRope = true; scale = QSCALE; }
        else if (bc < 40) { Bp = g_Wkf; Of = g_Kf; Nl = HK*HD; bcl = bc - 32;
                            doRope = true; }
        else              { Bp = g_Wvf; Of = g_Vf; Nl = HK*HD; bcl = bc - 40; }
    } else { Bp = Bp_; Nl = N_; bcl = bc; }

    float acc[2][8][4];
#pragma unroll
    for (int i = 0; i < 2; i++)
#pragma unroll
        for (int j = 0; j < 8; j++)
#pragma unroll
            for (int r = 0; r < 4; r++) acc[i][j][r] = 0.f;

    const int a_row = (lane & 7) + 8 * ((lane >> 3) & 1);
    const int a_k   = 8 * (lane >> 4);
    const int b_kr  = (lane & 7) + 8 * ((lane >> 3) & 1);
    const int b_n   = 8 * (lane >> 4);

    const int nkt = K / 32;

    const int ar0 = tid >> 2, ac0 = (tid & 3) * 8;
    const int bk0 = tid >> 4, bn0 = (tid & 15) * 8;
#define GEMM_ISSUE(KT, BUF) do {                                               \
    int _sb = (BUF) * G_ST;                                                    \
    _Pragma("unroll")                                                          \
    for (int _j = 0; _j < 2; _j++) {                                           \
        int _r = ar0 + _j * 64;                                                \
        size_t _go = (size_t)(br*128 + _r) * K + (KT)*32 + ac0;                \
        CP16(smb + (_sb + _r*G_SA + ac0)*2, Ap + _go);                         \
        int _k = bk0 + _j * 16;                                                \
        size_t _gb = (size_t)((KT)*32 + _k) * Nl + bcl*128 + bn0;              \
        CP16(smb + (_sb + G_B + _k*G_SB + bn0)*2, Bp + _gb);                   \
    } } while (0)

    GEMM_ISSUE(0, 0); CP_COMMIT;
    GEMM_ISSUE(1, 1); CP_COMMIT;
    GEMM_ISSUE(2, 2); CP_COMMIT;

    int buf = 0;
    for (int kt = 0; kt < nkt; kt++) {
        if (kt < nkt - 2)      { CP_WAIT2; }
        else if (kt == nkt - 2){ CP_WAIT1; }
        else                   { CP_WAIT0; }
        __syncthreads();
        const int sb = buf * G_ST;

#pragma unroll
        for (int ks = 0; ks < 2; ks++) {
            uint32_t af[2][4];
#pragma unroll
            for (int i = 0; i < 2; i++) {
                uint32_t addr = smb + (sb +
                    (wr*32 + i*16 + a_row)*G_SA + ks*16 + a_k) * 2;
                LDSM4(af[i][0], af[i][1], af[i][2], af[i][3], addr);
            }
#pragma unroll
            for (int jp = 0; jp < 4; jp++) {
                uint32_t bf[4];
                uint32_t addr = smb + (sb + G_B +
                    (ks*16 + b_kr)*G_SB + wc*64 + jp*16 + b_n) * 2;
                LDSM4T(bf[0], bf[1], bf[2], bf[3], addr);
#pragma unroll
                for (int i = 0; i < 2; i++) {
#pragma unroll
                    for (int jj = 0; jj < 2; jj++)
                        MMAF16(acc[i][2*jp + jj],
                               af[i][0],af[i][1],af[i][2],af[i][3],
                               bf[2*jj], bf[2*jj+1]);
                }
            }
        }
        __syncthreads();
        if (kt + 3 < nkt) { GEMM_ISSUE(kt + 3, buf); CP_COMMIT; }
        buf = (buf == 2) ? 0 : buf + 1;
    }

    const int g = lane >> 2, t = lane & 3;
#pragma unroll
    for (int i = 0; i < 2; i++) {
#pragma unroll
        for (int j = 0; j < 8; j++) {
            int row = br*128 + wr*32 + i*16 + g;
            int col = bcl*128 + wc*64 + j*8 + 2*t;
            float a0 = acc[i][j][0], a1 = acc[i][j][1];
            float a2 = acc[i][j][2], a3 = acc[i][j][3];
            if (QKV) {
                if (doRope) {
                    int s0 = row & (SEQ-1), s1 = (row+8) & (SEQ-1);
                    int d2 = (col & (HD-1)) >> 1;
                    float c0 = cosv[s0*64 + d2], sn0 = sinv[s0*64 + d2];
                    float c1 = cosv[s1*64 + d2], sn1 = sinv[s1*64 + d2];
                    float r;
                    r  = (a0*c0 - a1*sn0) * scale;
                    a1 = (a0*sn0 + a1*c0) * scale;  a0 = r;
                    r  = (a2*c1 - a3*sn1) * scale;
                    a3 = (a2*sn1 + a3*c1) * scale;  a2 = r;
                }
                *(uint32_t*)&Of[(size_t)row * Nl + col]     = pack2h(a0, a1);
                *(uint32_t*)&Of[(size_t)(row+8) * Nl + col] = pack2h(a2, a3);
            } else {
                *(float2*)&C[(size_t)row * Nl + col] = make_float2(a0, a1);
                *(float2*)&C[(size_t)(row+8) * Nl + col] = make_float2(a2, a3);
            }
        }
    }
}

// ---------------------------------------------------------------------------
// fp16 flash attention (R9/R14-proven, occ 2). BQ=128, BK=64, HD=128.
// ---------------------------------------------------------------------------
#define F_S   136
#define F_STG 17408
#define F_V   8704
#define F_SST 17408
#define FLASH_SMEM ((F_STG + 2*F_SST)*2)

__global__ __launch_bounds__(256,2) void flash_f16(
    const __half* __restrict__ Qf, const __half* __restrict__ Kf,
    const __half* __restrict__ Vf, __half* __restrict__ AOf)
{
    extern __shared__ __align__(16) __half smf[];
    const uint32_t smb = smem_u32(smf);

    const int tid = threadIdx.x;
    const int w = tid >> 5, lane = tid & 31;
    const int q0 = blockIdx.x * 128;
    const int b  = blockIdx.y >> 5;
    const int h  = blockIdx.y & 31;
    const int g  = h >> 2;

#pragma unroll
    for (int it = 0; it < 8; it++) {
        int idx = tid + it * 256;
        int r = idx >> 4, cc = (idx & 15) * 8;
        size_t go = ((size_t)((b*SEQ + q0 + r) * HQ + h)) * HD + cc;
        CP16(smb + (r*F_S + cc)*2, Qf + go);
    }
#define FLASH_ISSUE_KV(KB, BUF) do {                                           \
    int _sb = F_STG + (BUF) * F_SST;                                           \
    _Pragma("unroll")                                                          \
    for (int _it = 0; _it < 4; _it++) {                                        \
        int _idx = tid + _it * 256;                                            \
        int _r = _idx >> 4, _c = (_idx & 15) * 8;                              \
        size_t _go = ((size_t)((b*SEQ + (KB)*64 + _r) * HK + g)) * HD + _c;    \
        CP16(smb + (_sb + _r*F_S + _c)*2, Kf + _go);                           \
        CP16(smb + (_sb + F_V + _r*F_S + _c)*2, Vf + _go);                     \
    } } while (0)

    FLASH_ISSUE_KV(0, 0); CP_COMMIT;
    FLASH_ISSUE_KV(1, 1); CP_COMMIT;

    float oacc[16][4];
#pragma unroll
    for (int n = 0; n < 16; n++)
#pragma unroll
        for (int r = 0; r < 4; r++) oacc[n][r] = 0.f;
    float m0 = -1e30f, m1 = -1e30f, l0 = 0.f, l1 = 0.f;

    const int q_row = w*16 + (lane & 7) + 8*((lane >> 3) & 1);
    const int q_k   = 8 * (lane >> 4);
    const int k_row = (lane & 7) + 8*(lane >> 4);
    const int k_d   = 8 * ((lane >> 3) & 1);
    const int v_row = (lane & 7) + 8*((lane >> 3) & 1);
    const int v_d   = 8 * (lane >> 4);

    const int NKB = SEQ / 64;
    for (int kb = 0; kb < NKB; kb++) {
        if (kb < NKB - 2) { CP_WAIT1; } else { CP_WAIT0; }
        __syncthreads();
        const int sb = F_STG + (kb & 1) * F_SST;

        float sacc[8][4];
#pragma unroll
        for (int j = 0; j < 8; j++)
#pragma unroll
            for (int r = 0; r < 4; r++) sacc[j][r] = 0.f;

#pragma unroll
        for (int dks = 0; dks < 8; dks++) {
            uint32_t qf[4];
            uint32_t qa = smb + (q_row*F_S + dks*16 + q_k) * 2;
            LDSM4(qf[0], qf[1], qf[2], qf[3], qa);
#pragma unroll
            for (int sp = 0; sp < 4; sp++) {
                uint32_t kfr[4];
                uint32_t ka = smb + (sb + (sp*16 + k_row)*F_S + dks*16 + k_d) * 2;
                LDSM4(kfr[0], kfr[1], kfr[2], kfr[3], ka);
#pragma unroll
                for (int jj = 0; jj < 2; jj++)
                    MMAF16(sacc[2*sp + jj], qf[0],qf[1],qf[2],qf[3],
                           kfr[2*jj], kfr[2*jj+1]);
            }
        }

        float mx0 = m0, mx1 = m1;
#pragma unroll
        for (int j = 0; j < 8; j++) {
            mx0 = fmaxf(mx0, fmaxf(sacc[j][0], sacc[j][1]));
            mx1 = fmaxf(mx1, fmaxf(sacc[j][2], sacc[j][3]));
        }
        mx0 = fmaxf(mx0, __shfl_xor_sync(0xffffffffu, mx0, 1));
        mx0 = fmaxf(mx0, __shfl_xor_sync(0xffffffffu, mx0, 2));
        mx1 = fmaxf(mx1, __shfl_xor_sync(0xffffffffu, mx1, 1));
        mx1 = fmaxf(mx1, __shfl_xor_sync(0xffffffffu, mx1, 2));
        float sf0 = __expf(m0 - mx0), sf1 = __expf(m1 - mx1);
        m0 = mx0; m1 = mx1;
        float rs0 = 0.f, rs1 = 0.f;
#pragma unroll
        for (int j = 0; j < 8; j++) {
            sacc[j][0] = __expf(sacc[j][0] - m0);
            sacc[j][1] = __expf(sacc[j][1] - m0);
            sacc[j][2] = __expf(sacc[j][2] - m1);
            sacc[j][3] = __expf(sacc[j][3] - m1);
            rs0 += sacc[j][0] + sacc[j][1];
            rs1 += sacc[j][2] + sacc[j][3];
        }
        rs0 += __shfl_xor_sync(0xffffffffu, rs0, 1);
        rs0 += __shfl_xor_sync(0xffffffffu, rs0, 2);
        rs1 += __shfl_xor_sync(0xffffffffu, rs1, 1);
        rs1 += __shfl_xor_sync(0xffffffffu, rs1, 2);
        l0 = l0 * sf0 + rs0;
        l1 = l1 * sf1 + rs1;
#pragma unroll
        for (int n = 0; n < 16; n++) {
            oacc[n][0] *= sf0; oacc[n][1] *= sf0;
            oacc[n][2] *= sf1; oacc[n][3] *= sf1;
        }

#pragma unroll
        for (int ks = 0; ks < 4; ks++) {
            uint32_t ph[4];
            ph[0] = pack2h(sacc[2*ks  ][0], sacc[2*ks  ][1]);
            ph[1] = pack2h(sacc[2*ks  ][2], sacc[2*ks  ][3]);
            ph[2] = pack2h(sacc[2*ks+1][0], sacc[2*ks+1][1]);
            ph[3] = pack2h(sacc[2*ks+1][2], sacc[2*ks+1][3]);
#pragma unroll
            for (int np = 0; np < 8; np++) {
                uint32_t vf[4];
                uint32_t va = smb + (sb + F_V + (ks*16 + v_row)*F_S + np*16 + v_d) * 2;
                LDSM4T(vf[0], vf[1], vf[2], vf[3], va);
#pragma unroll
                for (int jj = 0; jj < 2; jj++)
                    MMAF16(oacc[2*np + jj], ph[0],ph[1],ph[2],ph[3],
                           vf[2*jj], vf[2*jj+1]);
            }
        }
        __syncthreads();
        if (kb + 2 < NKB) { FLASH_ISSUE_KV(kb + 2, kb & 1); CP_COMMIT; }
    }

    float il0 = 1.f / l0, il1 = 1.f / l1;
    const int ga = lane >> 2, t = lane & 3;
    const int qa = q0 + w*16 + ga;
#pragma unroll
    for (int n = 0; n < 16; n++) {
        int col = n*8 + 2*t;
        size_t base0 = ((size_t)((b*SEQ + qa)     * HQ + h)) * HD + col;
        size_t base1 = ((size_t)((b*SEQ + qa + 8) * HQ + h)) * HD + col;
        *(uint32_t*)&AOf[base0] = pack2h(oacc[n][0]*il0, oacc[n][1]*il0);
        *(uint32_t*)&AOf[base1] = pack2h(oacc[n][2]*il1, oacc[n][3]*il1);
    }
}

// ---------------------------------------------------------------------------
extern "C" void kernel_launch(void* const* d_in, const int* in_sizes, int n_in,
                              void* d_out, int out_size)
{
    const float* x    = (const float*)d_in[0];
    const float* wq   = (const float*)d_in[1];
    const float* wk   = (const float*)d_in[2];
    const float* wv   = (const float*)d_in[3];
    const float* wo   = (const float*)d_in[4];
    const float* fcos = (const float*)d_in[5];
    const float* fsin = (const float*)d_in[6];
    float* out = (float*)d_out;

    __half *Xf,*Wof,*Qf,*Kf,*Vf,*AOf;
    cudaGetSymbolAddress((void**)&Xf,  g_Xf);
    cudaGetSymbolAddress((void**)&Wof, g_Wof);
    cudaGetSymbolAddress((void**)&Qf,  g_Qf);
    cudaGetSymbolAddress((void**)&Kf,  g_Kf);
    cudaGetSymbolAddress((void**)&Vf,  g_Vf);
    cudaGetSymbolAddress((void**)&AOf, g_AOf);

    cudaFuncSetAttribute(gemm3<0>,  cudaFuncAttributeMaxDynamicSharedMemorySize, GEMM_SMEM3);
    cudaFuncSetAttribute(gemm3<1>,  cudaFuncAttributeMaxDynamicSharedMemorySize, GEMM_SMEM3);
    cudaFuncSetAttribute(flash_f16, cudaFuncAttributeMaxDynamicSharedMemorySize, FLASH_SMEM);

    // input conversion, MLP-4, one launch (grid.y = segment)
    cvt5<<<dim3(1024, 5), 256>>>(x, wq, wk, wv, wo);

    // fused QKV projection (rope + fp16 epilogues) — proven R9 config
    gemm3<1><<<dim3(48, MROWS/128), 256, GEMM_SMEM3>>>(
        Xf, nullptr, nullptr, fcos, fsin, MROWS, 0, DIM);

    // flash attention -> AO fp16 plane (occupancy 2) — proven R9 config
    flash_f16<<<dim3(SEQ/128, BATCH*HQ), 256, FLASH_SMEM>>>(Qf, Kf, Vf, AOf);

    // output projection — proven R9 config (128x128 tiles)
    gemm3<0><<<dim3(DIM/128, MROWS/128), 256, GEMM_SMEM3>>>(
        AOf, Wof, out, nullptr, nullptr, MROWS, DIM, DIM);
}